// round 16
// baseline (speedup 1.0000x reference)
#include <cuda_runtime.h>
#include <cuda_fp16.h>
#include <math.h>

// Problem constants
#define Bz      8192
#define NNETS   30
#define NNODES  20
#define NOUT    10
#define DOUT    16
#define INDIM   784
#define NCOL    600
#define NPAD    640

// Scratch: x split into fp16 hi/lo planes; W1 single fp16 plane (transposed)
__device__ unsigned short g_xh[Bz * INDIM];
__device__ unsigned short g_xl[Bz * INDIM];
__device__ unsigned short g_wh[NPAD * INDIM];
__device__ float g_b1p[NPAD];
__device__ float g_h1[Bz * NPAD];

// ---------------------------------------------------------------------------
// P0: x -> fp16 hi/lo planes
// ---------------------------------------------------------------------------
__global__ void prep_x_kernel(const float* __restrict__ x) {
    int i = blockIdx.x * blockDim.x + threadIdx.x;      // over float4
    if (i >= (Bz * INDIM) / 4) return;
    float4 v = ((const float4*)x)[i];
    unsigned short h[4], l[4];
    const float* vp = &v.x;
    #pragma unroll
    for (int j = 0; j < 4; j++) {
        __half hb = __float2half_rn(vp[j]);
        h[j] = __half_as_ushort(hb);
        l[j] = __half_as_ushort(__float2half_rn(vp[j] - __half2float(hb)));
    }
    uint2 ho, lo;
    ho.x = (unsigned)h[0] | ((unsigned)h[1] << 16);
    ho.y = (unsigned)h[2] | ((unsigned)h[3] << 16);
    lo.x = (unsigned)l[0] | ((unsigned)l[1] << 16);
    lo.y = (unsigned)l[2] | ((unsigned)l[3] << 16);
    ((uint2*)g_xh)[i] = ho;
    ((uint2*)g_xl)[i] = lo;
}

// ---------------------------------------------------------------------------
// P1: W1 [30][784][20] -> transposed fp16 plane [n=640][k=784] + bias pad
// ---------------------------------------------------------------------------
__global__ void prep_w_kernel(const float* __restrict__ W1, const float* __restrict__ b1) {
    int idx = blockIdx.x * blockDim.x + threadIdx.x;
    if (idx < NPAD * INDIM) {
        int n = idx / INDIM;
        int k = idx % INDIM;
        float w = 0.f;
        if (n < NCOL) {
            int net = n / NNODES, o = n % NNODES;
            w = W1[net * (INDIM * NNODES) + k * NNODES + o];
        }
        g_wh[idx] = __half_as_ushort(__float2half_rn(w));
    }
    if (idx < NPAD) g_b1p[idx] = (idx < NCOL) ? b1[idx] : 0.f;
}

// ---------------------------------------------------------------------------
// K1: tensor-core GEMM h1 = relu(x @ W1 + b1), 2xFP16 split, cp.async,
// block tile 128x64, 8 warps (warp tile 32x32), 3-stage pipeline. (R15)
// ---------------------------------------------------------------------------
#define ASTR    24
#define AH_OFF  0
#define AL_OFF  6144
#define BH_OFF  12288
#define STAGE_B 15360
#define GSMEM_B (3 * STAGE_B)

__device__ __forceinline__ void ldsm4(unsigned& r0, unsigned& r1, unsigned& r2, unsigned& r3,
                                      unsigned addr) {
    asm volatile("ldmatrix.sync.aligned.m8n8.x4.shared.b16 {%0,%1,%2,%3}, [%4];\n"
                 : "=r"(r0), "=r"(r1), "=r"(r2), "=r"(r3) : "r"(addr));
}
__device__ __forceinline__ void mma16816h(float* d, const unsigned* a, const unsigned* b) {
    asm volatile(
        "mma.sync.aligned.m16n8k16.row.col.f32.f16.f16.f32 "
        "{%0,%1,%2,%3}, {%4,%5,%6,%7}, {%8,%9}, {%0,%1,%2,%3};\n"
        : "+f"(d[0]), "+f"(d[1]), "+f"(d[2]), "+f"(d[3])
        : "r"(a[0]), "r"(a[1]), "r"(a[2]), "r"(a[3]), "r"(b[0]), "r"(b[1]));
}
__device__ __forceinline__ void cpasync16(unsigned dst, const void* src) {
    asm volatile("cp.async.ca.shared.global [%0], [%1], 16;\n" :: "r"(dst), "l"(src));
}

__global__ __launch_bounds__(256) void gemm1_tc_kernel() {
    extern __shared__ __align__(16) char gsm[];
    const unsigned smBase = (unsigned)__cvta_generic_to_shared(gsm);

    const int tid  = threadIdx.x;
    const int bm   = blockIdx.x & 63;
    const int bn   = blockIdx.x >> 6;
    const int warp = tid >> 5;
    const int lane = tid & 31;
    const int wm   = warp >> 1;
    const int wn   = warp & 1;

    const int ar = tid >> 1;
    const int ac = (tid & 1) * 8;
    const unsigned short* xhp = g_xh + (size_t)(bm * 128 + ar) * INDIM + ac;
    const unsigned short* xlp = g_xl + (size_t)(bm * 128 + ar) * INDIM + ac;
    const unsigned short* whp = g_wh + (size_t)(bn * 64 + ar) * INDIM + ac;
    const unsigned ahDst = smBase + AH_OFF + (ar * ASTR + ac) * 2;
    const unsigned alDst = smBase + AL_OFF + (ar * ASTR + ac) * 2;
    const unsigned bhDst = smBase + BH_OFF + (ar * ASTR + ac) * 2;

    float acc[2][4][4];
    #pragma unroll
    for (int i = 0; i < 2; i++)
        #pragma unroll
        for (int j = 0; j < 4; j++)
            #pragma unroll
            for (int q = 0; q < 4; q++) acc[i][j][q] = 0.f;

    const int mi = lane >> 3, lr = lane & 7;
    const int a_row = lr + ((mi & 1) << 3);
    const int a_cb  = (mi >> 1) << 4;
    const int b_row = lr + ((mi >> 1) << 3);
    const int b_cb  = (mi & 1) << 4;

    unsigned aAddrH[2], aAddrL[2], bAddrH[2];
    #pragma unroll
    for (int mt = 0; mt < 2; mt++) {
        int r = wm * 32 + mt * 16 + a_row;
        aAddrH[mt] = smBase + AH_OFF + r * ASTR * 2 + a_cb;
        aAddrL[mt] = smBase + AL_OFF + r * ASTR * 2 + a_cb;
    }
    #pragma unroll
    for (int p = 0; p < 2; p++) {
        int r = wn * 32 + p * 16 + b_row;
        bAddrH[p] = smBase + BH_OFF + r * ASTR * 2 + b_cb;
    }

    auto issue = [&](int kt, int s) {
        const unsigned so = (unsigned)(s * STAGE_B);
        cpasync16(ahDst + so, xhp + kt * 16);
        cpasync16(alDst + so, xlp + kt * 16);
        if (tid < 128) cpasync16(bhDst + so, whp + kt * 16);
        asm volatile("cp.async.commit_group;\n" ::: "memory");
    };

    issue(0, 0);
    issue(1, 1);

    for (int kt = 0; kt < 49; kt++) {
        const unsigned so = (unsigned)((kt % 3) * STAGE_B);

        if (kt < 48) {
            asm volatile("cp.async.wait_group 1;\n" ::: "memory");
        } else {
            asm volatile("cp.async.wait_group 0;\n" ::: "memory");
        }
        __syncthreads();

        if (kt + 2 < 49) issue(kt + 2, (kt + 2) % 3);

        unsigned ah[2][4], al[2][4], bh[4][2];
        #pragma unroll
        for (int mt = 0; mt < 2; mt++) {
            ldsm4(ah[mt][0], ah[mt][1], ah[mt][2], ah[mt][3], aAddrH[mt] + so);
            ldsm4(al[mt][0], al[mt][1], al[mt][2], al[mt][3], aAddrL[mt] + so);
        }
        #pragma unroll
        for (int p = 0; p < 2; p++) {
            ldsm4(bh[2*p][0], bh[2*p][1], bh[2*p+1][0], bh[2*p+1][1], bAddrH[p] + so);
        }

        #pragma unroll
        for (int mt = 0; mt < 2; mt++)
            #pragma unroll
            for (int nt = 0; nt < 4; nt++) {
                mma16816h(acc[mt][nt], ah[mt], bh[nt]);
                mma16816h(acc[mt][nt], al[mt], bh[nt]);
            }
    }

    const int g = lane >> 2, t = lane & 3;
    #pragma unroll
    for (int mt = 0; mt < 2; mt++) {
        #pragma unroll
        for (int nt = 0; nt < 4; nt++) {
            int col = bn * 64 + wn * 32 + nt * 8 + t * 2;
            float2 bias = *(const float2*)&g_b1p[col];
            int row0 = bm * 128 + wm * 32 + mt * 16 + g;
            float2 v0, v1;
            v0.x = fmaxf(acc[mt][nt][0] + bias.x, 0.f);
            v0.y = fmaxf(acc[mt][nt][1] + bias.y, 0.f);
            v1.x = fmaxf(acc[mt][nt][2] + bias.x, 0.f);
            v1.y = fmaxf(acc[mt][nt][3] + bias.y, 0.f);
            *(float2*)&g_h1[(size_t)row0 * NPAD + col]       = v0;
            *(float2*)&g_h1[(size_t)(row0 + 8) * NPAD + col] = v1;
        }
    }
}

// ---------------------------------------------------------------------------
// K3 v11: R8 structure with RMB=4, 512 threads, 2 blocks/SM (113 KB smem).
// Latency/barrier exposure of one block overlaps with the other block.
// ---------------------------------------------------------------------------
#define RMB     4
#define PRI_F   (RMB * 300 * 20)     // 24000
#define REG2_F  (RMB * 600)          // 2400
#define PB_F    (RMB * 300)          // 1200
#define VV_F    (RMB * 160)          // 640
#define RT_SMEM_BYTES ((PRI_F + REG2_F + PB_F + VV_F) * 4)   // 112960
#define RT_THREADS 512

__global__ __launch_bounds__(RT_THREADS, 2) void routing_kernel(const float* __restrict__ W2,
                                                                const float* __restrict__ b2,
                                                                const float* __restrict__ rw,
                                                                float* __restrict__ out) {
    extern __shared__ float sm[];
    float* pri  = sm;                 // [mb][pair][20]
    float* reg2 = sm + PRI_F;
    float* pb   = reg2 + REG2_F;      // [mb][300]
    float* vv   = pb + PB_F;          // [mb][160]
    float* us   = reg2;               // [mb][600]  (live: stage1..priors)
    float* lg   = reg2;               // [mb][300]  (live: it0 phase d..end)
    float* W2s  = pri;                // [30][400]  (live: stage1 only)
    float* b2s  = pri + 12000;        // [600]

    const int tid = threadIdx.x;
    const int b0  = blockIdx.x * RMB;

    // ---- stage 1a: W2 + b2 into smem (coalesced) ----
    for (int i = tid; i < 3150; i += RT_THREADS) {
        if (i < 3000) ((float4*)W2s)[i] = ((const float4*)W2)[i];
        else          ((float4*)b2s)[i - 3000] = ((const float4*)b2)[i - 3000];
    }
    __syncthreads();

    // ---- stage 1b: u = squash(relu(h1 @ W2 + b2)), 120 threads ----
    if (tid < NNETS * RMB) {
        const int n  = tid >> 2;
        const int mb = tid & 3;

        float4 h4[5];
        const float4* hp = (const float4*)(g_h1 + (size_t)(b0 + mb) * NPAD + n * NNODES);
        #pragma unroll
        for (int q = 0; q < 5; q++) h4[q] = hp[q];
        const float* h = (const float*)h4;

        float4 a4[5];
        const float4* bp = (const float4*)(b2s + n * NNODES);
        #pragma unroll
        for (int q = 0; q < 5; q++) a4[q] = bp[q];
        float* acc = (float*)a4;

        const float4* w4 = (const float4*)(W2s + n * 400);
        #pragma unroll
        for (int d = 0; d < NNODES; d++) {
            float hd = h[d];
            #pragma unroll
            for (int q = 0; q < 5; q++) {
                float4 w = w4[d * 5 + q];
                acc[q * 4 + 0] = fmaf(hd, w.x, acc[q * 4 + 0]);
                acc[q * 4 + 1] = fmaf(hd, w.y, acc[q * 4 + 1]);
                acc[q * 4 + 2] = fmaf(hd, w.z, acc[q * 4 + 2]);
                acc[q * 4 + 3] = fmaf(hd, w.w, acc[q * 4 + 3]);
            }
        }
        float sq = 0.f;
        #pragma unroll
        for (int e = 0; e < NNODES; e++) {
            acc[e] = fmaxf(acc[e], 0.f);
            sq = fmaf(acc[e], acc[e], sq);
        }
        float f = sqrtf(sq) / (1.f + sq);
        float* up = us + mb * 600 + n * NNODES;
        #pragma unroll
        for (int q = 0; q < 5; q++) {
            float4 o;
            o.x = acc[q * 4 + 0] * f;
            o.y = acc[q * 4 + 1] * f;
            o.z = acc[q * 4 + 2] * f;
            o.w = acc[q * 4 + 3] * f;
            *(float4*)&up[q * 4] = o;
        }
    }
    __syncthreads();   // u ready; W2s (pri) dead

    // ---- stage 2: priors into pri (1200 tasks over 512 threads) ----
    #pragma unroll
    for (int g = 0; g < 3; g++) {
        int task = tid + RT_THREADS * g;
        if (task < 1200) {
            const int kq   = task & 3;
            const int pair = task >> 2;
            const int n = pair % NNETS;
            const float* rwp = rw + (size_t)pair * 320 + kq * 4;
            const float* ub  = us + n * 20;

            float acc[RMB][4];
            #pragma unroll
            for (int mb = 0; mb < RMB; mb++) {
                acc[mb][0] = 0.f; acc[mb][1] = 0.f; acc[mb][2] = 0.f; acc[mb][3] = 0.f;
            }
            #pragma unroll
            for (int dq = 0; dq < 5; dq++) {
                float4 w0 = *(const float4*)&rwp[(dq * 4 + 0) * 16];
                float4 w1 = *(const float4*)&rwp[(dq * 4 + 1) * 16];
                float4 w2 = *(const float4*)&rwp[(dq * 4 + 2) * 16];
                float4 w3 = *(const float4*)&rwp[(dq * 4 + 3) * 16];
                #pragma unroll
                for (int mb = 0; mb < RMB; mb++) {
                    float4 uq = *(const float4*)&ub[mb * 600 + dq * 4];
                    acc[mb][0] = fmaf(w0.x, uq.x, acc[mb][0]);
                    acc[mb][1] = fmaf(w0.y, uq.x, acc[mb][1]);
                    acc[mb][2] = fmaf(w0.z, uq.x, acc[mb][2]);
                    acc[mb][3] = fmaf(w0.w, uq.x, acc[mb][3]);
                    acc[mb][0] = fmaf(w1.x, uq.y, acc[mb][0]);
                    acc[mb][1] = fmaf(w1.y, uq.y, acc[mb][1]);
                    acc[mb][2] = fmaf(w1.z, uq.y, acc[mb][2]);
                    acc[mb][3] = fmaf(w1.w, uq.y, acc[mb][3]);
                    acc[mb][0] = fmaf(w2.x, uq.z, acc[mb][0]);
                    acc[mb][1] = fmaf(w2.y, uq.z, acc[mb][1]);
                    acc[mb][2] = fmaf(w2.z, uq.z, acc[mb][2]);
                    acc[mb][3] = fmaf(w2.w, uq.z, acc[mb][3]);
                    acc[mb][0] = fmaf(w3.x, uq.w, acc[mb][0]);
                    acc[mb][1] = fmaf(w3.y, uq.w, acc[mb][1]);
                    acc[mb][2] = fmaf(w3.z, uq.w, acc[mb][2]);
                    acc[mb][3] = fmaf(w3.w, uq.w, acc[mb][3]);
                }
            }
            #pragma unroll
            for (int mb = 0; mb < RMB; mb++)
                *(float4*)&pri[mb * 6000 + pair * 20 + kq * 4] =
                    make_float4(acc[mb][0], acc[mb][1], acc[mb][2], acc[mb][3]);
        }
    }
    __syncthreads();   // pri ready; us dead -> lg region free

    // ---- stage 3: routing iterations ----
    for (int it = 0; it < 3; it++) {
        if (it > 0) {
            // softmax over o per (mb, n): 120 threads
            if (tid < RMB * NNETS) {
                int mb = tid / NNETS, n = tid % NNETS;
                const float* L = lg + mb * 300 + n;
                float lo[NOUT];
                float m = -1e30f;
                #pragma unroll
                for (int o = 0; o < NOUT; o++) { lo[o] = L[o * 30]; m = fmaxf(m, lo[o]); }
                float e[NOUT], ss = 0.f;
                #pragma unroll
                for (int o = 0; o < NOUT; o++) { e[o] = __expf(lo[o] - m); ss += e[o]; }
                float inv = 1.f / ss;
                float* P = pb + mb * 300 + n;
                #pragma unroll
                for (int o = 0; o < NOUT; o++) P[o * 30] = e[o] * inv;
            }
            __syncthreads();
        }

        // phase b/c: 320 threads (mb, o, k-pair); squash via 3 shfls
        if (tid < RMB * 80) {
            const int mb  = tid / 80;
            const int r   = tid % 80;
            const int o   = r >> 3;
            const int kh8 = r & 7;
            const int k0  = kh8 * 2;
            const float* PR = pri + mb * 6000 + o * 600 + k0;
            const float* P  = pb  + mb * 300  + o * 30;

            float s0 = 0.f, s1 = 0.f;
            #pragma unroll 6
            for (int n = 0; n < NNETS; n++) {
                float p = (it == 0) ? 0.1f : P[n];
                float2 q = *(const float2*)&PR[n * 20];
                s0 = fmaf(p, q.x, s0);
                s1 = fmaf(p, q.y, s1);
            }
            float sq = fmaf(s0, s0, s1 * s1);
            sq += __shfl_xor_sync(0xffffffffu, sq, 1);
            sq += __shfl_xor_sync(0xffffffffu, sq, 2);
            sq += __shfl_xor_sync(0xffffffffu, sq, 4);
            float f = sqrtf(sq) / (1.f + sq);
            float v0 = s0 * f, v1 = s1 * f;

            if (it < 2) {
                *(float2*)&vv[mb * 160 + o * 16 + k0] = make_float2(v0, v1);
            } else {
                *(float2*)&out[(size_t)(b0 + mb) * 160 + o * 16 + k0] =
                    make_float2(v0, v1);
            }
        }

        if (it < 2) {
            __syncthreads();
            // phase d: logits update, 1200 tasks over 512 threads
            #pragma unroll
            for (int pass = 0; pass < 3; pass++) {
                int idx = tid + pass * RT_THREADS;
                if (idx < RMB * 300) {
                    int mb = idx / 300;
                    int r  = idx % 300;
                    int o  = r / 30;
                    const float4* PR4 = (const float4*)&pri[mb * 6000 + r * 20];
                    const float4* V4  = (const float4*)&vv[mb * 160 + o * 16];
                    float dl = 0.f;
                    #pragma unroll
                    for (int q = 0; q < 4; q++) {
                        float4 a = PR4[q];
                        float4 b = V4[q];
                        dl = fmaf(a.x, b.x, dl);
                        dl = fmaf(a.y, b.y, dl);
                        dl = fmaf(a.z, b.z, dl);
                        dl = fmaf(a.w, b.w, dl);
                    }
                    if (it == 0) lg[idx] = dl;
                    else         lg[idx] += dl;
                }
            }
            __syncthreads();
        }
    }
}

// ---------------------------------------------------------------------------
extern "C" void kernel_launch(void* const* d_in, const int* in_sizes, int n_in,
                              void* d_out, int out_size) {
    const float* x  = (const float*)d_in[0];
    const float* W1 = (const float*)d_in[1];
    const float* b1 = (const float*)d_in[2];
    const float* W2 = (const float*)d_in[3];
    const float* b2 = (const float*)d_in[4];
    const float* rw = (const float*)d_in[5];
    float* out = (float*)d_out;

    (void)in_sizes; (void)n_in; (void)out_size;

    prep_x_kernel<<<(Bz * INDIM / 4 + 255) / 256, 256>>>(x);
    prep_w_kernel<<<(NPAD * INDIM + 255) / 256, 256>>>(W1, b1);

    cudaFuncSetAttribute(gemm1_tc_kernel,
                         cudaFuncAttributeMaxDynamicSharedMemorySize, GSMEM_B);
    gemm1_tc_kernel<<<64 * 10, 256, GSMEM_B>>>();

    cudaFuncSetAttribute(routing_kernel,
                         cudaFuncAttributeMaxDynamicSharedMemorySize, RT_SMEM_BYTES);
    routing_kernel<<<Bz / RMB, RT_THREADS, RT_SMEM_BYTES>>>(W2, b2, rw, out);
}

// round 17
// speedup vs baseline: 1.1478x; 1.1478x over previous
#include <cuda_runtime.h>
#include <cuda_fp16.h>
#include <math.h>

// Problem constants
#define Bz      8192
#define NNETS   30
#define NNODES  20
#define NOUT    10
#define DOUT    16
#define INDIM   784
#define NCOL    600
#define NPAD    640

// Scratch: x split into fp16 hi/lo planes; W1 single fp16 plane (transposed)
__device__ unsigned short g_xh[Bz * INDIM];
__device__ unsigned short g_xl[Bz * INDIM];
__device__ unsigned short g_wh[NPAD * INDIM];
__device__ float g_b1p[NPAD];
__device__ float g_h1[Bz * NPAD];

// ---------------------------------------------------------------------------
// P0: merged prep — x -> fp16 hi/lo planes; W1 -> transposed fp16 + bias pad
// ---------------------------------------------------------------------------
__global__ void prep_kernel(const float* __restrict__ x,
                            const float* __restrict__ W1,
                            const float* __restrict__ b1) {
    int i = blockIdx.x * blockDim.x + threadIdx.x;
    // x planes: 1605632 float4s
    if (i < (Bz * INDIM) / 4) {
        float4 v = ((const float4*)x)[i];
        unsigned short h[4], l[4];
        const float* vp = &v.x;
        #pragma unroll
        for (int j = 0; j < 4; j++) {
            __half hb = __float2half_rn(vp[j]);
            h[j] = __half_as_ushort(hb);
            l[j] = __half_as_ushort(__float2half_rn(vp[j] - __half2float(hb)));
        }
        uint2 ho, lo;
        ho.x = (unsigned)h[0] | ((unsigned)h[1] << 16);
        ho.y = (unsigned)h[2] | ((unsigned)h[3] << 16);
        lo.x = (unsigned)l[0] | ((unsigned)l[1] << 16);
        lo.y = (unsigned)l[2] | ((unsigned)l[3] << 16);
        ((uint2*)g_xh)[i] = ho;
        ((uint2*)g_xl)[i] = lo;
    }
    // W1 plane: 501760 elements (done by first blocks in parallel with x work)
    if (i < NPAD * INDIM) {
        int n = i / INDIM;
        int k = i % INDIM;
        float w = 0.f;
        if (n < NCOL) {
            int net = n / NNODES, o = n % NNODES;
            w = W1[net * (INDIM * NNODES) + k * NNODES + o];
        }
        g_wh[i] = __half_as_ushort(__float2half_rn(w));
    }
    if (i < NPAD) g_b1p[i] = (i < NCOL) ? b1[i] : 0.f;
}

// ---------------------------------------------------------------------------
// K1: tensor-core GEMM h1 = relu(x @ W1 + b1), 2xFP16 split, cp.async,
// block tile 128x64, 8 warps (warp tile 32x32), 3-stage pipeline, 2 blocks/SM.
// ---------------------------------------------------------------------------
#define ASTR    24
#define AH_OFF  0
#define AL_OFF  6144
#define BH_OFF  12288
#define STAGE_B 15360
#define GSMEM_B (3 * STAGE_B)

__device__ __forceinline__ void ldsm4(unsigned& r0, unsigned& r1, unsigned& r2, unsigned& r3,
                                      unsigned addr) {
    asm volatile("ldmatrix.sync.aligned.m8n8.x4.shared.b16 {%0,%1,%2,%3}, [%4];\n"
                 : "=r"(r0), "=r"(r1), "=r"(r2), "=r"(r3) : "r"(addr));
}
__device__ __forceinline__ void mma16816h(float* d, const unsigned* a, const unsigned* b) {
    asm volatile(
        "mma.sync.aligned.m16n8k16.row.col.f32.f16.f16.f32 "
        "{%0,%1,%2,%3}, {%4,%5,%6,%7}, {%8,%9}, {%0,%1,%2,%3};\n"
        : "+f"(d[0]), "+f"(d[1]), "+f"(d[2]), "+f"(d[3])
        : "r"(a[0]), "r"(a[1]), "r"(a[2]), "r"(a[3]), "r"(b[0]), "r"(b[1]));
}
__device__ __forceinline__ void cpasync16(unsigned dst, const void* src) {
    asm volatile("cp.async.ca.shared.global [%0], [%1], 16;\n" :: "r"(dst), "l"(src));
}

__global__ __launch_bounds__(256, 2) void gemm1_tc_kernel() {
    extern __shared__ __align__(16) char gsm[];
    const unsigned smBase = (unsigned)__cvta_generic_to_shared(gsm);

    const int tid  = threadIdx.x;
    const int bm   = blockIdx.x & 63;
    const int bn   = blockIdx.x >> 6;
    const int warp = tid >> 5;
    const int lane = tid & 31;
    const int wm   = warp >> 1;
    const int wn   = warp & 1;

    const int ar = tid >> 1;
    const int ac = (tid & 1) * 8;
    const unsigned short* xhp = g_xh + (size_t)(bm * 128 + ar) * INDIM + ac;
    const unsigned short* xlp = g_xl + (size_t)(bm * 128 + ar) * INDIM + ac;
    const unsigned short* whp = g_wh + (size_t)(bn * 64 + ar) * INDIM + ac;
    const unsigned ahDst = smBase + AH_OFF + (ar * ASTR + ac) * 2;
    const unsigned alDst = smBase + AL_OFF + (ar * ASTR + ac) * 2;
    const unsigned bhDst = smBase + BH_OFF + (ar * ASTR + ac) * 2;

    float acc[2][4][4];
    #pragma unroll
    for (int i = 0; i < 2; i++)
        #pragma unroll
        for (int j = 0; j < 4; j++)
            #pragma unroll
            for (int q = 0; q < 4; q++) acc[i][j][q] = 0.f;

    const int mi = lane >> 3, lr = lane & 7;
    const int a_row = lr + ((mi & 1) << 3);
    const int a_cb  = (mi >> 1) << 4;
    const int b_row = lr + ((mi >> 1) << 3);
    const int b_cb  = (mi & 1) << 4;

    unsigned aAddrH[2], aAddrL[2], bAddrH[2];
    #pragma unroll
    for (int mt = 0; mt < 2; mt++) {
        int r = wm * 32 + mt * 16 + a_row;
        aAddrH[mt] = smBase + AH_OFF + r * ASTR * 2 + a_cb;
        aAddrL[mt] = smBase + AL_OFF + r * ASTR * 2 + a_cb;
    }
    #pragma unroll
    for (int p = 0; p < 2; p++) {
        int r = wn * 32 + p * 16 + b_row;
        bAddrH[p] = smBase + BH_OFF + r * ASTR * 2 + b_cb;
    }

    auto issue = [&](int kt, int s) {
        const unsigned so = (unsigned)(s * STAGE_B);
        cpasync16(ahDst + so, xhp + kt * 16);
        cpasync16(alDst + so, xlp + kt * 16);
        if (tid < 128) cpasync16(bhDst + so, whp + kt * 16);
        asm volatile("cp.async.commit_group;\n" ::: "memory");
    };

    issue(0, 0);
    issue(1, 1);

    for (int kt = 0; kt < 49; kt++) {
        const unsigned so = (unsigned)((kt % 3) * STAGE_B);

        if (kt < 48) {
            asm volatile("cp.async.wait_group 1;\n" ::: "memory");
        } else {
            asm volatile("cp.async.wait_group 0;\n" ::: "memory");
        }
        __syncthreads();

        if (kt + 2 < 49) issue(kt + 2, (kt + 2) % 3);

        unsigned ah[2][4], al[2][4], bh[4][2];
        #pragma unroll
        for (int mt = 0; mt < 2; mt++) {
            ldsm4(ah[mt][0], ah[mt][1], ah[mt][2], ah[mt][3], aAddrH[mt] + so);
            ldsm4(al[mt][0], al[mt][1], al[mt][2], al[mt][3], aAddrL[mt] + so);
        }
        #pragma unroll
        for (int p = 0; p < 2; p++) {
            ldsm4(bh[2*p][0], bh[2*p][1], bh[2*p+1][0], bh[2*p+1][1], bAddrH[p] + so);
        }

        #pragma unroll
        for (int mt = 0; mt < 2; mt++)
            #pragma unroll
            for (int nt = 0; nt < 4; nt++) {
                mma16816h(acc[mt][nt], ah[mt], bh[nt]);
                mma16816h(acc[mt][nt], al[mt], bh[nt]);
            }
    }

    const int g = lane >> 2, t = lane & 3;
    #pragma unroll
    for (int mt = 0; mt < 2; mt++) {
        #pragma unroll
        for (int nt = 0; nt < 4; nt++) {
            int col = bn * 64 + wn * 32 + nt * 8 + t * 2;
            float2 bias = *(const float2*)&g_b1p[col];
            int row0 = bm * 128 + wm * 32 + mt * 16 + g;
            float2 v0, v1;
            v0.x = fmaxf(acc[mt][nt][0] + bias.x, 0.f);
            v0.y = fmaxf(acc[mt][nt][1] + bias.y, 0.f);
            v1.x = fmaxf(acc[mt][nt][2] + bias.x, 0.f);
            v1.y = fmaxf(acc[mt][nt][3] + bias.y, 0.f);
            *(float2*)&g_h1[(size_t)row0 * NPAD + col]       = v0;
            *(float2*)&g_h1[(size_t)(row0 + 8) * NPAD + col] = v1;
        }
    }
}

// ---------------------------------------------------------------------------
// K3: FUSED layer2 + priors + routing — EXACT R8 version (128 us, frozen).
// ---------------------------------------------------------------------------
#define RMB     8
#define PRI_F   (RMB * 300 * 20)
#define REG2_F  (RMB * 600)
#define PB_F    (RMB * 300)
#define VV_F    (RMB * 160)
#define RT_SMEM_BYTES ((PRI_F + REG2_F + PB_F + VV_F) * 4)
#define RT_THREADS 768

__global__ __launch_bounds__(RT_THREADS, 1) void routing_kernel(const float* __restrict__ W2,
                                                                const float* __restrict__ b2,
                                                                const float* __restrict__ rw,
                                                                float* __restrict__ out) {
    extern __shared__ float sm[];
    float* pri  = sm;
    float* reg2 = sm + PRI_F;
    float* pb   = reg2 + REG2_F;
    float* vv   = pb + PB_F;
    float* us   = reg2;
    float* lg   = reg2;
    float* W2s  = pri;
    float* b2s  = pri + 12000;

    const int tid = threadIdx.x;
    const int b0  = blockIdx.x * RMB;

    for (int i = tid; i < 3150; i += RT_THREADS) {
        if (i < 3000) ((float4*)W2s)[i] = ((const float4*)W2)[i];
        else          ((float4*)b2s)[i - 3000] = ((const float4*)b2)[i - 3000];
    }
    __syncthreads();

    if (tid < 240) {
        const int n  = tid >> 3;
        const int mb = tid & 7;

        float4 h4[5];
        const float4* hp = (const float4*)(g_h1 + (size_t)(b0 + mb) * NPAD + n * NNODES);
        #pragma unroll
        for (int q = 0; q < 5; q++) h4[q] = hp[q];
        const float* h = (const float*)h4;

        float4 a4[5];
        const float4* bp = (const float4*)(b2s + n * NNODES);
        #pragma unroll
        for (int q = 0; q < 5; q++) a4[q] = bp[q];
        float* acc = (float*)a4;

        const float4* w4 = (const float4*)(W2s + n * 400);
        #pragma unroll
        for (int d = 0; d < NNODES; d++) {
            float hd = h[d];
            #pragma unroll
            for (int q = 0; q < 5; q++) {
                float4 w = w4[d * 5 + q];
                acc[q * 4 + 0] = fmaf(hd, w.x, acc[q * 4 + 0]);
                acc[q * 4 + 1] = fmaf(hd, w.y, acc[q * 4 + 1]);
                acc[q * 4 + 2] = fmaf(hd, w.z, acc[q * 4 + 2]);
                acc[q * 4 + 3] = fmaf(hd, w.w, acc[q * 4 + 3]);
            }
        }
        float sq = 0.f;
        #pragma unroll
        for (int e = 0; e < NNODES; e++) {
            acc[e] = fmaxf(acc[e], 0.f);
            sq = fmaf(acc[e], acc[e], sq);
        }
        float f = sqrtf(sq) / (1.f + sq);
        float* up = us + mb * 600 + n * NNODES;
        #pragma unroll
        for (int q = 0; q < 5; q++) {
            float4 o;
            o.x = acc[q * 4 + 0] * f;
            o.y = acc[q * 4 + 1] * f;
            o.z = acc[q * 4 + 2] * f;
            o.w = acc[q * 4 + 3] * f;
            *(float4*)&up[q * 4] = o;
        }
    }
    __syncthreads();

    #pragma unroll
    for (int g = 0; g < 2; g++) {
        int task = tid + RT_THREADS * g;
        if (task < 1200) {
            const int kq   = task & 3;
            const int pair = task >> 2;
            const int n = pair % NNETS;
            const float* rwp = rw + (size_t)pair * 320 + kq * 4;
            const float* ub  = us + n * 20;

            float acc[RMB][4];
            #pragma unroll
            for (int mb = 0; mb < RMB; mb++) {
                acc[mb][0] = 0.f; acc[mb][1] = 0.f; acc[mb][2] = 0.f; acc[mb][3] = 0.f;
            }
            #pragma unroll
            for (int dq = 0; dq < 5; dq++) {
                float4 w0 = *(const float4*)&rwp[(dq * 4 + 0) * 16];
                float4 w1 = *(const float4*)&rwp[(dq * 4 + 1) * 16];
                float4 w2 = *(const float4*)&rwp[(dq * 4 + 2) * 16];
                float4 w3 = *(const float4*)&rwp[(dq * 4 + 3) * 16];
                #pragma unroll
                for (int mb = 0; mb < RMB; mb++) {
                    float4 uq = *(const float4*)&ub[mb * 600 + dq * 4];
                    acc[mb][0] = fmaf(w0.x, uq.x, acc[mb][0]);
                    acc[mb][1] = fmaf(w0.y, uq.x, acc[mb][1]);
                    acc[mb][2] = fmaf(w0.z, uq.x, acc[mb][2]);
                    acc[mb][3] = fmaf(w0.w, uq.x, acc[mb][3]);
                    acc[mb][0] = fmaf(w1.x, uq.y, acc[mb][0]);
                    acc[mb][1] = fmaf(w1.y, uq.y, acc[mb][1]);
                    acc[mb][2] = fmaf(w1.z, uq.y, acc[mb][2]);
                    acc[mb][3] = fmaf(w1.w, uq.y, acc[mb][3]);
                    acc[mb][0] = fmaf(w2.x, uq.z, acc[mb][0]);
                    acc[mb][1] = fmaf(w2.y, uq.z, acc[mb][1]);
                    acc[mb][2] = fmaf(w2.z, uq.z, acc[mb][2]);
                    acc[mb][3] = fmaf(w2.w, uq.z, acc[mb][3]);
                    acc[mb][0] = fmaf(w3.x, uq.w, acc[mb][0]);
                    acc[mb][1] = fmaf(w3.y, uq.w, acc[mb][1]);
                    acc[mb][2] = fmaf(w3.z, uq.w, acc[mb][2]);
                    acc[mb][3] = fmaf(w3.w, uq.w, acc[mb][3]);
                }
            }
            #pragma unroll
            for (int mb = 0; mb < RMB; mb++)
                *(float4*)&pri[mb * 6000 + pair * 20 + kq * 4] =
                    make_float4(acc[mb][0], acc[mb][1], acc[mb][2], acc[mb][3]);
        }
    }
    __syncthreads();

    for (int it = 0; it < 3; it++) {
        if (it > 0) {
            if (tid < RMB * NNETS) {
                int mb = tid / NNETS, n = tid % NNETS;
                const float* L = lg + mb * 300 + n;
                float lo[NOUT];
                float m = -1e30f;
                #pragma unroll
                for (int o = 0; o < NOUT; o++) { lo[o] = L[o * 30]; m = fmaxf(m, lo[o]); }
                float e[NOUT], ss = 0.f;
                #pragma unroll
                for (int o = 0; o < NOUT; o++) { e[o] = __expf(lo[o] - m); ss += e[o]; }
                float inv = 1.f / ss;
                float* P = pb + mb * 300 + n;
                #pragma unroll
                for (int o = 0; o < NOUT; o++) P[o * 30] = e[o] * inv;
            }
            __syncthreads();
        }

        if (tid < 640) {
            const int mb  = tid / 80;
            const int r   = tid % 80;
            const int o   = r >> 3;
            const int kh8 = r & 7;
            const int k0  = kh8 * 2;
            const float* PR = pri + mb * 6000 + o * 600 + k0;
            const float* P  = pb  + mb * 300  + o * 30;

            float s0 = 0.f, s1 = 0.f;
            #pragma unroll 6
            for (int n = 0; n < NNETS; n++) {
                float p = (it == 0) ? 0.1f : P[n];
                float2 q = *(const float2*)&PR[n * 20];
                s0 = fmaf(p, q.x, s0);
                s1 = fmaf(p, q.y, s1);
            }
            float sq = fmaf(s0, s0, s1 * s1);
            sq += __shfl_xor_sync(0xffffffffu, sq, 1);
            sq += __shfl_xor_sync(0xffffffffu, sq, 2);
            sq += __shfl_xor_sync(0xffffffffu, sq, 4);
            float f = sqrtf(sq) / (1.f + sq);
            float v0 = s0 * f, v1 = s1 * f;

            if (it < 2) {
                *(float2*)&vv[mb * 160 + o * 16 + k0] = make_float2(v0, v1);
            } else {
                *(float2*)&out[(size_t)(b0 + mb) * 160 + o * 16 + k0] =
                    make_float2(v0, v1);
            }
        }

        if (it < 2) {
            __syncthreads();
            #pragma unroll
            for (int pass = 0; pass < 4; pass++) {
                int idx = tid + pass * RT_THREADS;
                if (idx < 2400) {
                    int mb = idx / 300;
                    int r  = idx % 300;
                    int o  = r / 30;
                    const float4* PR4 = (const float4*)&pri[mb * 6000 + r * 20];
                    const float4* V4  = (const float4*)&vv[mb * 160 + o * 16];
                    float dl = 0.f;
                    #pragma unroll
                    for (int q = 0; q < 4; q++) {
                        float4 a = PR4[q];
                        float4 b = V4[q];
                        dl = fmaf(a.x, b.x, dl);
                        dl = fmaf(a.y, b.y, dl);
                        dl = fmaf(a.z, b.z, dl);
                        dl = fmaf(a.w, b.w, dl);
                    }
                    if (it == 0) lg[idx] = dl;
                    else         lg[idx] += dl;
                }
            }
            __syncthreads();
        }
    }
}

// ---------------------------------------------------------------------------
extern "C" void kernel_launch(void* const* d_in, const int* in_sizes, int n_in,
                              void* d_out, int out_size) {
    const float* x  = (const float*)d_in[0];
    const float* W1 = (const float*)d_in[1];
    const float* b1 = (const float*)d_in[2];
    const float* W2 = (const float*)d_in[3];
    const float* b2 = (const float*)d_in[4];
    const float* rw = (const float*)d_in[5];
    float* out = (float*)d_out;

    (void)in_sizes; (void)n_in; (void)out_size;

    prep_kernel<<<(Bz * INDIM / 4 + 255) / 256, 256>>>(x, W1, b1);

    cudaFuncSetAttribute(gemm1_tc_kernel,
                         cudaFuncAttributeMaxDynamicSharedMemorySize, GSMEM_B);
    gemm1_tc_kernel<<<64 * 10, 256, GSMEM_B>>>();

    cudaFuncSetAttribute(routing_kernel,
                         cudaFuncAttributeMaxDynamicSharedMemorySize, RT_SMEM_BYTES);
    routing_kernel<<<Bz / RMB, RT_THREADS, RT_SMEM_BYTES>>>(W2, b2, rw, out);
}